// round 2
// baseline (speedup 1.0000x reference)
#include <cuda_runtime.h>
#include <math.h>

#define BB 512
#define DD 2048
#define KK 128
#define PP 5
#define NN (KK * PP)      // 640
#define OUTW (DD + KK)    // 2176

// scratch (no cudaMalloc allowed)
__device__ float g_actv[BB * NN];   // [B, K*P], pre-scaled by log2(e)
__device__ float g_scale[NN];

// ---------------------------------------------------------------------------
// 1) column scales: scale[kp] = exp(lws[kp]) / ||theta[:,kp]|| * log2(e)
//    grid: 20 blocks x 256 threads, 32 cols per block, 8 d-stripes
// ---------------------------------------------------------------------------
__global__ void scale_kernel(const float* __restrict__ theta,
                             const float* __restrict__ lws) {
    int c = threadIdx.x & 31;        // col within group
    int q = threadIdx.x >> 5;        // d stripe 0..7
    int col = blockIdx.x * 32 + c;
    float s = 0.f;
    for (int d = q; d < DD; d += 8) {
        float v = theta[d * NN + col];
        s += v * v;
    }
    __shared__ float red[8][32];
    red[q][c] = s;
    __syncthreads();
    if (q == 0) {
        float t = 0.f;
#pragma unroll
        for (int i = 0; i < 8; i++) t += red[i][c];
        g_scale[col] = __expf(lws[col]) * rsqrtf(t) * 1.4426950408889634f;
    }
}

// ---------------------------------------------------------------------------
// 2) SGEMM: g_actv[b, n] = scale[n] * sum_d x[b,d] * theta[d, n]
//    64x64 tile, BK=32, 256 threads, 4x4 microtile.
//    grid: (640/64, 512/64) = (10, 8)
// ---------------------------------------------------------------------------
#define BM 64
#define BN 64
#define BK 32
#define BMP 68   // padded row for As (16B-aligned, reduced store conflicts)

__global__ __launch_bounds__(256, 1)
void gemm_kernel(const float* __restrict__ x, const float* __restrict__ theta) {
    __shared__ float As[BK][BMP];   // A transposed: As[k][row]
    __shared__ float Bs[BK][BN];    // Bs[k][col]

    const int tid = threadIdx.x;
    const int tx = tid & 15;        // col group 0..15
    const int ty = tid >> 4;        // row group 0..15
    const int rowBase = blockIdx.y * BM;
    const int colBase = blockIdx.x * BN;

    float acc[4][4] = {};

    for (int k0 = 0; k0 < DD; k0 += BK) {
        // load A tile: 64 rows x 32 cols = 512 float4, 2 per thread
#pragma unroll
        for (int l = 0; l < 2; l++) {
            int idx = tid + l * 256;      // 0..511 over 64 x 8 float4s
            int r = idx >> 3;
            int c4 = idx & 7;
            float4 v = *(const float4*)&x[(rowBase + r) * DD + k0 + c4 * 4];
            As[c4 * 4 + 0][r] = v.x;
            As[c4 * 4 + 1][r] = v.y;
            As[c4 * 4 + 2][r] = v.z;
            As[c4 * 4 + 3][r] = v.w;
        }
        // load B tile: 32 rows x 64 cols = 512 float4, 2 per thread
#pragma unroll
        for (int l = 0; l < 2; l++) {
            int idx = tid + l * 256;
            int r = idx >> 4;             // 0..31
            int c4 = idx & 15;            // 0..15
            float4 v = *(const float4*)&theta[(k0 + r) * NN + colBase + c4 * 4];
            *(float4*)&Bs[r][c4 * 4] = v;
        }
        __syncthreads();

#pragma unroll
        for (int kk = 0; kk < BK; kk++) {
            float4 av = *(const float4*)&As[kk][ty * 4];
            float4 bv = *(const float4*)&Bs[kk][tx * 4];
            float a[4] = {av.x, av.y, av.z, av.w};
            float b[4] = {bv.x, bv.y, bv.z, bv.w};
#pragma unroll
            for (int i = 0; i < 4; i++)
#pragma unroll
                for (int j = 0; j < 4; j++)
                    acc[i][j] += a[i] * b[j];
        }
        __syncthreads();
    }

#pragma unroll
    for (int i = 0; i < 4; i++) {
        int row = rowBase + ty * 4 + i;
#pragma unroll
        for (int j = 0; j < 4; j++) {
            int col = colBase + tx * 4 + j;
            g_actv[row * NN + col] = acc[i][j] * g_scale[col];
        }
    }
}

// ---------------------------------------------------------------------------
// 3) pairwise: f[i,k] = sum_j exp(-sum_p |actv[i,k,p]-actv[j,k,p]|) - 1 + bias[k]
//    (actv already scaled by log2 e, so exp(-s) == 2^(-s) -> single EX2)
//    grid: 128 blocks (one per k), 512 threads (one per row i)
// ---------------------------------------------------------------------------
__global__ __launch_bounds__(512, 1)
void pairwise_kernel(const float* __restrict__ bias, float* __restrict__ out) {
    int k = blockIdx.x;
    int i = threadIdx.x;
    __shared__ float sA[BB][8];

    const float* ap = &g_actv[i * NN + k * PP];
    float a0 = ap[0], a1 = ap[1], a2 = ap[2], a3 = ap[3], a4 = ap[4];
    sA[i][0] = a0; sA[i][1] = a1; sA[i][2] = a2; sA[i][3] = a3; sA[i][4] = a4;
    __syncthreads();

    float acc = 0.f;
#pragma unroll 8
    for (int j = 0; j < BB; j++) {
        float4 v = *(const float4*)&sA[j][0];
        float b4 = sA[j][4];
        float s = fabsf(a0 - v.x) + fabsf(a1 - v.y) + fabsf(a2 - v.z) +
                  fabsf(a3 - v.w) + fabsf(a4 - b4);
        float e;
        asm("ex2.approx.ftz.f32 %0, %1;" : "=f"(e) : "f"(-s));
        acc += e;
    }
    // diagonal contributed exp2(0) == 1 exactly; reference kills it with 1e6
    out[i * OUTW + DD + k] = acc - 1.0f + bias[k];
}

// ---------------------------------------------------------------------------
// 4) copy x into out[:, 0:2048]
// ---------------------------------------------------------------------------
__global__ void copy_x_kernel(const float* __restrict__ x, float* __restrict__ out) {
    int idx = blockIdx.x * blockDim.x + threadIdx.x;    // over B*D/4 float4s
    int row = idx / (DD / 4);
    int c4 = idx - row * (DD / 4);
    *(float4*)&out[row * OUTW + c4 * 4] = ((const float4*)x)[idx];
}

// ---------------------------------------------------------------------------
extern "C" void kernel_launch(void* const* d_in, const int* in_sizes, int n_in,
                              void* d_out, int out_size) {
    const float* x     = (const float*)d_in[0];   // [512, 2048]
    const float* theta = (const float*)d_in[1];   // [2048, 128, 5]
    const float* lws   = (const float*)d_in[2];   // [128, 5]
    const float* bias  = (const float*)d_in[3];   // [128]
    float* out = (float*)d_out;                   // [512, 2176]

    scale_kernel<<<20, 256>>>(theta, lws);
    gemm_kernel<<<dim3(NN / BN, BB / BM), 256>>>(x, theta);
    pairwise_kernel<<<KK, BB>>>(bias, out);
    copy_x_kernel<<<(BB * DD / 4) / 256, 256>>>(x, out);
}

// round 5
// speedup vs baseline: 1.1567x; 1.1567x over previous
#include <cuda_runtime.h>
#include <cstdint>
#include <math.h>

#define BB 512
#define DD 2048
#define KK 128
#define PP 5
#define NN (KK * PP)      // 640
#define OUTW (DD + KK)    // 2176

// ---------------- scratch (no cudaMalloc allowed) ----------------
__device__ float g_actv[BB * NN];     // [B, 640], pre-scaled by log2(e)
__device__ float g_scale[NN];
__device__ float g_xr[BB * DD];       // x rounded to tf32 (rna)
__device__ float g_bt[NN * DD];       // theta^T * scale * log2e, rounded to tf32

__device__ __forceinline__ float rna_tf32(float v) {
    uint32_t u;
    asm("cvt.rna.tf32.f32 %0, %1;" : "=r"(u) : "f"(v));
    return __uint_as_float(u);
}

// ---------------------------------------------------------------------------
// 1) column scales: scale[kp] = exp(lws)/||theta[:,kp]|| * log2(e)
// ---------------------------------------------------------------------------
__global__ void scale_kernel(const float* __restrict__ theta,
                             const float* __restrict__ lws) {
    int c = threadIdx.x & 31;
    int q = threadIdx.x >> 5;
    int col = blockIdx.x * 32 + c;
    float s = 0.f;
    for (int d = q; d < DD; d += 8) {
        float v = theta[d * NN + col];
        s += v * v;
    }
    __shared__ float red[8][32];
    red[q][c] = s;
    __syncthreads();
    if (q == 0) {
        float t = 0.f;
#pragma unroll
        for (int i = 0; i < 8; i++) t += red[i][c];
        g_scale[col] = __expf(lws[col]) * rsqrtf(t) * 1.4426950408889634f;
    }
}

// ---------------------------------------------------------------------------
// 2a) round x to tf32 (rna) into g_xr
// ---------------------------------------------------------------------------
__global__ void round_x_kernel(const float* __restrict__ x) {
    const float4* xi = (const float4*)x;
    float4* xo = (float4*)g_xr;
    int n4 = BB * DD / 4;
    for (int i = blockIdx.x * blockDim.x + threadIdx.x; i < n4;
         i += gridDim.x * blockDim.x) {
        float4 v = xi[i];
        v.x = rna_tf32(v.x); v.y = rna_tf32(v.y);
        v.z = rna_tf32(v.z); v.w = rna_tf32(v.w);
        xo[i] = v;
    }
}

// ---------------------------------------------------------------------------
// 2b) transpose theta [2048,640] -> g_bt [640,2048], fold scale, round to tf32
// ---------------------------------------------------------------------------
__global__ void transpose_kernel(const float* __restrict__ theta) {
    __shared__ float t[32][33];
    int n0 = blockIdx.x * 32, d0 = blockIdx.y * 32;
    int tx = threadIdx.x, ty = threadIdx.y;
    float sc = g_scale[n0 + tx];
#pragma unroll
    for (int i = 0; i < 4; i++) {
        int r = ty + i * 8;
        t[r][tx] = theta[(size_t)(d0 + r) * NN + n0 + tx] * sc;
    }
    __syncthreads();
#pragma unroll
    for (int i = 0; i < 4; i++) {
        int r = ty + i * 8;
        g_bt[(size_t)(n0 + r) * DD + d0 + tx] = rna_tf32(t[tx][r]);
    }
}

// ---------------------------------------------------------------------------
// 3) tf32 mma.sync GEMM: actv[m,n] = sum_d xr[m,d] * bt[n,d]
//    CTA tile 32x64, K-stage 32, 128 threads (4 warps, warp tile m16 x n32)
//    grid (640/64, 512/32) = (10, 16) = 160 CTAs
//    smem holds A/B in mma FRAGMENT layout (m16n8k8.tf32):
//      A block (wm,ks): 128 floats; elem A[r][k] at lane=(r&7)*4+(k&3),
//                       reg=((r>>3)&1) + 2*((k>>2)&1); addr=lane*4+reg
//      B block (nb,ks):  64 floats; elem B[n][k] at lane=(n&7)*4+(k&3),
//                       reg=(k>>2)&1; addr=lane*2+reg
// ---------------------------------------------------------------------------
#define TM 32
#define TN 64
#define STAGE_FLOATS 3072   // A 1024 + B 2048 floats = 12KB

__device__ __forceinline__ void mma_tf32(float* c, float4 a, float2 b) {
    asm volatile(
        "mma.sync.aligned.m16n8k8.row.col.f32.tf32.tf32.f32 "
        "{%0,%1,%2,%3}, {%4,%5,%6,%7}, {%8,%9}, {%0,%1,%2,%3};"
        : "+f"(c[0]), "+f"(c[1]), "+f"(c[2]), "+f"(c[3])
        : "r"(__float_as_uint(a.x)), "r"(__float_as_uint(a.y)),
          "r"(__float_as_uint(a.z)), "r"(__float_as_uint(a.w)),
          "r"(__float_as_uint(b.x)), "r"(__float_as_uint(b.y)));
}

__global__ __launch_bounds__(128, 1) void gemm_mma_kernel() {
    __shared__ float sm[2 * STAGE_FLOATS];

    const int tid = threadIdx.x;
    const int lane = tid & 31;
    const int wid = tid >> 5;
    const int wm = wid & 1;       // warp row (m16)
    const int wn = wid >> 1;      // warp col (n32)
    const int mBase = blockIdx.y * TM;
    const int nBase = blockIdx.x * TN;

    // ---- producer address precompute ----
    // A: 2 float4 per thread per stage; float4 = A[row][kc*4 .. kc*4+3]
    int aDst[2];
    const float4* aSrc[2];
#pragma unroll
    for (int j = 0; j < 2; j++) {
        int idx = tid + j * 128;          // 0..255
        int row = idx >> 3;               // 0..31
        int kc = idx & 7;                 // float4 col 0..7
        // block = (row>>4)*4 + (kc>>1); lane=(row&7)*4+(k&3); reg=((row>>3)&1)+2*(kc&1)
        aDst[j] = ((row >> 4) * 4 + (kc >> 1)) * 128
                + (row & 7) * 16 + ((row >> 3) & 1) + 2 * (kc & 1);
        aSrc[j] = (const float4*)(g_xr + (size_t)(mBase + row) * DD) + kc;
    }
    // B: 4 float4 per thread per stage; float4 = B[n][kc*4 .. kc*4+3]
    int bDst[4];
    const float4* bSrc[4];
#pragma unroll
    for (int j = 0; j < 4; j++) {
        int idx = tid + j * 128;          // 0..511
        int n = idx >> 3;                 // 0..63
        int kc = idx & 7;
        bDst[j] = 1024 + ((n >> 3) * 4 + (kc >> 1)) * 64
                + (n & 7) * 8 + (kc & 1);
        bSrc[j] = (const float4*)(g_bt + (size_t)(nBase + n) * DD) + kc;
    }

    float acc[4][4] = {};

    // ---- stage 0 fill ----
    {
        float4 ra[2], rb[4];
#pragma unroll
        for (int j = 0; j < 2; j++) ra[j] = aSrc[j][0];
#pragma unroll
        for (int j = 0; j < 4; j++) rb[j] = bSrc[j][0];
#pragma unroll
        for (int j = 0; j < 2; j++) {
            sm[aDst[j] + 0]  = ra[j].x;
            sm[aDst[j] + 4]  = ra[j].y;
            sm[aDst[j] + 8]  = ra[j].z;
            sm[aDst[j] + 12] = ra[j].w;
        }
#pragma unroll
        for (int j = 0; j < 4; j++) {
            sm[bDst[j] + 0] = rb[j].x;
            sm[bDst[j] + 2] = rb[j].y;
            sm[bDst[j] + 4] = rb[j].z;
            sm[bDst[j] + 6] = rb[j].w;
        }
    }
    __syncthreads();

    const int aFragBase = wm * 4 * 128 + lane * 4;            // + ks*128
    const int bFragBase = 1024 + wn * 4 * 4 * 64 + lane * 2;  // + (nb*4+ks)*64

#pragma unroll 2
    for (int it = 0; it < 64; ++it) {
        int cur = it & 1;
        float* s = sm + cur * STAGE_FLOATS;

        float4 ra[2], rb[4];
        if (it < 63) {
#pragma unroll
            for (int j = 0; j < 2; j++) ra[j] = aSrc[j][(it + 1) * 8];
#pragma unroll
            for (int j = 0; j < 4; j++) rb[j] = bSrc[j][(it + 1) * 8];
        }

#pragma unroll
        for (int ks = 0; ks < 4; ++ks) {
            float4 a = *(const float4*)(s + aFragBase + ks * 128);
#pragma unroll
            for (int nb = 0; nb < 4; ++nb) {
                float2 b = *(const float2*)(s + bFragBase + (nb * 4 + ks) * 64);
                mma_tf32(acc[nb], a, b);
            }
        }

        if (it < 63) {
            float* d = sm + (cur ^ 1) * STAGE_FLOATS;
#pragma unroll
            for (int j = 0; j < 2; j++) {
                d[aDst[j] + 0]  = ra[j].x;
                d[aDst[j] + 4]  = ra[j].y;
                d[aDst[j] + 8]  = ra[j].z;
                d[aDst[j] + 12] = ra[j].w;
            }
#pragma unroll
            for (int j = 0; j < 4; j++) {
                d[bDst[j] + 0] = rb[j].x;
                d[bDst[j] + 2] = rb[j].y;
                d[bDst[j] + 4] = rb[j].z;
                d[bDst[j] + 6] = rb[j].w;
            }
        }
        __syncthreads();
    }

    // ---- epilogue: write actv ----
    int row0 = mBase + wm * 16 + (lane >> 2);
    int col0 = nBase + wn * 32 + (lane & 3) * 2;
#pragma unroll
    for (int nb = 0; nb < 4; ++nb) {
        int col = col0 + nb * 8;
        *(float2*)&g_actv[(size_t)row0 * NN + col] =
            make_float2(acc[nb][0], acc[nb][1]);
        *(float2*)&g_actv[(size_t)(row0 + 8) * NN + col] =
            make_float2(acc[nb][2], acc[nb][3]);
    }
}

// ---------------------------------------------------------------------------
// 4) pairwise: f[i,k] = sum_j exp2(-sum_p |a_ip - a_jp|) - 1 + bias[k]
// ---------------------------------------------------------------------------
__global__ __launch_bounds__(512, 1)
void pairwise_kernel(const float* __restrict__ bias, float* __restrict__ out) {
    int k = blockIdx.x;
    int i = threadIdx.x;
    __shared__ float sA[BB][8];

    const float* ap = &g_actv[i * NN + k * PP];
    float a0 = ap[0], a1 = ap[1], a2 = ap[2], a3 = ap[3], a4 = ap[4];
    sA[i][0] = a0; sA[i][1] = a1; sA[i][2] = a2; sA[i][3] = a3; sA[i][4] = a4;
    __syncthreads();

    float acc = 0.f;
#pragma unroll 8
    for (int j = 0; j < BB; j++) {
        float4 v = *(const float4*)&sA[j][0];
        float b4 = sA[j][4];
        float s = fabsf(a0 - v.x) + fabsf(a1 - v.y) + fabsf(a2 - v.z) +
                  fabsf(a3 - v.w) + fabsf(a4 - b4);
        float e;
        asm("ex2.approx.ftz.f32 %0, %1;" : "=f"(e) : "f"(-s));
        acc += e;
    }
    out[i * OUTW + DD + k] = acc - 1.0f + bias[k];
}

// ---------------------------------------------------------------------------
// 5) copy x into out[:, 0:2048]
// ---------------------------------------------------------------------------
__global__ void copy_x_kernel(const float* __restrict__ x, float* __restrict__ out) {
    int n4 = BB * DD / 4;
    for (int idx = blockIdx.x * blockDim.x + threadIdx.x; idx < n4;
         idx += gridDim.x * blockDim.x) {
        int row = idx >> 9;
        int c4 = idx & 511;
        *(float4*)&out[(size_t)row * OUTW + c4 * 4] = ((const float4*)x)[idx];
    }
}

// ---------------------------------------------------------------------------
extern "C" void kernel_launch(void* const* d_in, const int* in_sizes, int n_in,
                              void* d_out, int out_size) {
    const float* x     = (const float*)d_in[0];   // [512, 2048]
    const float* theta = (const float*)d_in[1];   // [2048, 128, 5]
    const float* lws   = (const float*)d_in[2];   // [128, 5]
    const float* bias  = (const float*)d_in[3];   // [128]
    float* out = (float*)d_out;                   // [512, 2176]

    scale_kernel<<<20, 256>>>(theta, lws);
    round_x_kernel<<<256, 256>>>(x);
    transpose_kernel<<<dim3(NN / 32, DD / 32), dim3(32, 8)>>>(theta);
    gemm_mma_kernel<<<dim3(NN / TN, BB / TM), 128>>>();
    pairwise_kernel<<<KK, BB>>>(bias, out);
    copy_x_kernel<<<256, 256>>>(x, out);
}

// round 6
// speedup vs baseline: 2.0482x; 1.7706x over previous
#include <cuda_runtime.h>
#include <cstdint>
#include <math.h>

#define BB 512
#define DD 2048
#define KK 128
#define PP 5
#define NN (KK * PP)      // 640
#define OUTW (DD + KK)    // 2176

#define SPLIT 4
#define KC (DD / SPLIT)   // 512 K per CTA
#define TM 64
#define TN 160
#define ROWP 36           // padded row stride (floats): conflict-free + 16B-aligned
#define B_OFF (TM * ROWP)            // 2304 floats
#define STG_FLOATS ((TM + TN) * ROWP) // 8064 floats = 32256 B
#define NSTAGE 4
#define GEMM_SMEM (NSTAGE * STG_FLOATS * 4)  // 129024 B

// ---------------- scratch (no cudaMalloc allowed) ----------------
__device__ float g_part[SPLIT * BB * NN];  // K-split partial actv (xlog2e folded)
__device__ float g_scale[NN];
__device__ float g_xr[BB * DD];            // x rounded to tf32 (rna)
__device__ float g_bt[NN * DD];            // theta^T * scale * log2e, tf32

__device__ __forceinline__ float rna_tf32(float v) {
    uint32_t u;
    asm("cvt.rna.tf32.f32 %0, %1;" : "=r"(u) : "f"(v));
    return __uint_as_float(u);
}
__device__ __forceinline__ uint32_t s2u(const void* p) {
    uint32_t a;
    asm("{ .reg .u64 t; cvta.to.shared.u64 t, %1; cvt.u32.u64 %0, t; }"
        : "=r"(a) : "l"(p));
    return a;
}

// ---------------------------------------------------------------------------
// 1) column scales: scale[kp] = exp(lws)/||theta[:,kp]|| * log2(e)
// ---------------------------------------------------------------------------
__global__ void scale_kernel(const float* __restrict__ theta,
                             const float* __restrict__ lws) {
    int c = threadIdx.x & 31;
    int q = threadIdx.x >> 5;
    int col = blockIdx.x * 32 + c;
    float s = 0.f;
    for (int d = q; d < DD; d += 8) {
        float v = theta[d * NN + col];
        s += v * v;
    }
    __shared__ float red[8][32];
    red[q][c] = s;
    __syncthreads();
    if (q == 0) {
        float t = 0.f;
#pragma unroll
        for (int i = 0; i < 8; i++) t += red[i][c];
        g_scale[col] = __expf(lws[col]) * rsqrtf(t) * 1.4426950408889634f;
    }
}

// ---------------------------------------------------------------------------
// 2a) round x -> g_xr (tf32 rna), AND copy raw x -> out[:, 0:2048] (fused)
// ---------------------------------------------------------------------------
__global__ void round_x_kernel(const float* __restrict__ x, float* __restrict__ out) {
    const float4* xi = (const float4*)x;
    float4* xo = (float4*)g_xr;
    int n4 = BB * DD / 4;
    for (int i = blockIdx.x * blockDim.x + threadIdx.x; i < n4;
         i += gridDim.x * blockDim.x) {
        float4 v = xi[i];
        int row = i >> 9;
        int c4 = i & 511;
        *(float4*)&out[(size_t)row * OUTW + c4 * 4] = v;   // raw copy
        v.x = rna_tf32(v.x); v.y = rna_tf32(v.y);
        v.z = rna_tf32(v.z); v.w = rna_tf32(v.w);
        xo[i] = v;
    }
}

// ---------------------------------------------------------------------------
// 2b) transpose theta [2048,640] -> g_bt [640,2048], fold scale, round to tf32
// ---------------------------------------------------------------------------
__global__ void transpose_kernel(const float* __restrict__ theta) {
    __shared__ float t[32][33];
    int n0 = blockIdx.x * 32, d0 = blockIdx.y * 32;
    int tx = threadIdx.x, ty = threadIdx.y;
    float sc = g_scale[n0 + tx];
#pragma unroll
    for (int i = 0; i < 4; i++) {
        int r = ty + i * 8;
        t[r][tx] = theta[(size_t)(d0 + r) * NN + n0 + tx] * sc;
    }
    __syncthreads();
#pragma unroll
    for (int i = 0; i < 4; i++) {
        int r = ty + i * 8;
        g_bt[(size_t)(n0 + r) * DD + d0 + tx] = rna_tf32(t[tx][r]);
    }
}

// ---------------------------------------------------------------------------
// 3) tf32 mma.sync GEMM with cp.async 4-stage ring.
//    CTA: 64m x 160n x K=512 (split over blockIdx.z). 256 thr, 8 warps.
//    Warp grid 2m x 4n, warp tile 32x40 (2 m16-sub x 5 n8-sub), acc 40 regs.
//    smem: row-major tiles, rows padded to 36 floats -> conflict-free LDS.32.
//    grid (640/160, 512/64, SPLIT) = (4, 8, 4) = 128 CTAs, one wave.
// ---------------------------------------------------------------------------
__device__ __forceinline__ void mma_tf32(float* c,
                                         float a0, float a1, float a2, float a3,
                                         float b0, float b1) {
    asm volatile(
        "mma.sync.aligned.m16n8k8.row.col.f32.tf32.tf32.f32 "
        "{%0,%1,%2,%3}, {%4,%5,%6,%7}, {%8,%9}, {%0,%1,%2,%3};"
        : "+f"(c[0]), "+f"(c[1]), "+f"(c[2]), "+f"(c[3])
        : "r"(__float_as_uint(a0)), "r"(__float_as_uint(a1)),
          "r"(__float_as_uint(a2)), "r"(__float_as_uint(a3)),
          "r"(__float_as_uint(b0)), "r"(__float_as_uint(b1)));
}

__global__ __launch_bounds__(256, 1) void gemm_mma_kernel() {
    extern __shared__ float sm[];
    const int tid = threadIdx.x, lane = tid & 31, wid = tid >> 5;
    const int wm = wid & 1;        // 0..1 (m warp, 32 rows)
    const int wn = wid >> 1;       // 0..3 (n warp, 40 cols)
    const int mBase = blockIdx.y * TM;
    const int nBase = blockIdx.x * TN;
    const int split = blockIdx.z;
    const size_t kbase0 = (size_t)split * KC;

    // ---- producer setup: 7 cp.async(16B) chunks per thread per stage ----
    size_t srcg[7];
    uint32_t dsts[7];
    const uint32_t sb = s2u(sm);
#pragma unroll
    for (int q = 0; q < 7; q++) {
        int c = tid + q * 256;                 // 0..1791
        const float* src;
        uint32_t d;
        if (c < 512) {                          // A: 64 rows x 8 chunks
            int r = c >> 3, p = c & 7;
            src = g_xr + (size_t)(mBase + r) * DD + kbase0 + p * 4;
            d = (uint32_t)(r * ROWP + p * 4) * 4;
        } else {                                // B: 160 rows x 8 chunks
            int cb = c - 512;
            int n = cb >> 3, p = cb & 7;
            src = g_bt + (size_t)(nBase + n) * DD + kbase0 + p * 4;
            d = (uint32_t)(B_OFF + n * ROWP + p * 4) * 4;
        }
        srcg[q] = __cvta_generic_to_global(src);
        dsts[q] = sb + d;
    }

#define LOAD_STAGE(it_) do {                                               \
    uint32_t soff_ = (uint32_t)(((it_) & 3) * (STG_FLOATS * 4));           \
    size_t go_ = (size_t)(it_) * 128;                                      \
    _Pragma("unroll")                                                      \
    for (int q_ = 0; q_ < 7; q_++)                                         \
        asm volatile("cp.async.cg.shared.global [%0], [%1], 16;"           \
                     :: "r"(dsts[q_] + soff_), "l"(srcg[q_] + go_));       \
    asm volatile("cp.async.commit_group;" ::: "memory");                   \
} while (0)

    // prologue: stages 0..2
    LOAD_STAGE(0);
    LOAD_STAGE(1);
    LOAD_STAGE(2);

    float acc[5][2][4] = {};
    const int aRow = wm * 32 + (lane >> 2);
    const int kCol = lane & 3;
    const int bRow = wn * 40 + (lane >> 2);

    const int NIT = KC / 32;   // 16
#pragma unroll 1
    for (int it = 0; it < NIT; ++it) {
        asm volatile("cp.async.wait_group 2;" ::: "memory");
        __syncthreads();
        const float* s = sm + (it & 3) * STG_FLOATS;

#pragma unroll
        for (int ks = 0; ks < 4; ++ks) {
            float a[2][4];
#pragma unroll
            for (int ms = 0; ms < 2; ++ms) {
                const float* ap = s + (aRow + ms * 16) * ROWP + ks * 8 + kCol;
                a[ms][0] = ap[0];
                a[ms][1] = ap[8 * ROWP];
                a[ms][2] = ap[4];
                a[ms][3] = ap[8 * ROWP + 4];
            }
#pragma unroll
            for (int nb = 0; nb < 5; ++nb) {
                const float* bp = s + B_OFF + (bRow + nb * 8) * ROWP + ks * 8 + kCol;
                float b0 = bp[0], b1 = bp[4];
                mma_tf32(acc[nb][0], a[0][0], a[0][1], a[0][2], a[0][3], b0, b1);
                mma_tf32(acc[nb][1], a[1][0], a[1][1], a[1][2], a[1][3], b0, b1);
            }
        }
        __syncthreads();
        if (it + 3 < NIT) LOAD_STAGE(it + 3);
        else asm volatile("cp.async.commit_group;" ::: "memory");
    }

    // ---- epilogue: write K-split partials ----
    float* op = g_part + (size_t)split * BB * NN;
    const int row0 = mBase + wm * 32 + (lane >> 2);
    const int col0 = nBase + wn * 40 + (lane & 3) * 2;
#pragma unroll
    for (int nb = 0; nb < 5; ++nb) {
#pragma unroll
        for (int ms = 0; ms < 2; ++ms) {
            int row = row0 + ms * 16;
            int col = col0 + nb * 8;
            *(float2*)&op[(size_t)row * NN + col] =
                make_float2(acc[nb][ms][0], acc[nb][ms][1]);
            *(float2*)&op[(size_t)(row + 8) * NN + col] =
                make_float2(acc[nb][ms][2], acc[nb][ms][3]);
        }
    }
#undef LOAD_STAGE
}

// ---------------------------------------------------------------------------
// 4) pairwise: f[i,k] = sum_j exp2(-sum_p |a_ip - a_jp|) - 1 + bias[k]
//    a = sum of SPLIT partials (loaded once per thread).
// ---------------------------------------------------------------------------
__global__ __launch_bounds__(512, 1)
void pairwise_kernel(const float* __restrict__ bias, float* __restrict__ out) {
    int k = blockIdx.x;
    int i = threadIdx.x;
    __shared__ float sA[BB][8];

    float a0 = 0.f, a1 = 0.f, a2 = 0.f, a3 = 0.f, a4 = 0.f;
#pragma unroll
    for (int s = 0; s < SPLIT; s++) {
        const float* p = g_part + (size_t)s * BB * NN + (size_t)i * NN + k * PP;
        a0 += p[0]; a1 += p[1]; a2 += p[2]; a3 += p[3]; a4 += p[4];
    }
    sA[i][0] = a0; sA[i][1] = a1; sA[i][2] = a2; sA[i][3] = a3; sA[i][4] = a4;
    __syncthreads();

    float acc = 0.f;
#pragma unroll 8
    for (int j = 0; j < BB; j++) {
        float4 v = *(const float4*)&sA[j][0];
        float b4 = sA[j][4];
        float s = fabsf(a0 - v.x) + fabsf(a1 - v.y) + fabsf(a2 - v.z) +
                  fabsf(a3 - v.w) + fabsf(a4 - b4);
        float e;
        asm("ex2.approx.ftz.f32 %0, %1;" : "=f"(e) : "f"(-s));
        acc += e;
    }
    out[(size_t)i * OUTW + DD + k] = acc - 1.0f + bias[k];
}

// ---------------------------------------------------------------------------
extern "C" void kernel_launch(void* const* d_in, const int* in_sizes, int n_in,
                              void* d_out, int out_size) {
    const float* x     = (const float*)d_in[0];   // [512, 2048]
    const float* theta = (const float*)d_in[1];   // [2048, 128, 5]
    const float* lws   = (const float*)d_in[2];   // [128, 5]
    const float* bias  = (const float*)d_in[3];   // [128]
    float* out = (float*)d_out;                   // [512, 2176]

    cudaFuncSetAttribute(gemm_mma_kernel,
                         cudaFuncAttributeMaxDynamicSharedMemorySize, GEMM_SMEM);

    scale_kernel<<<20, 256>>>(theta, lws);
    round_x_kernel<<<256, 256>>>(x, out);
    transpose_kernel<<<dim3(NN / 32, DD / 32), dim3(32, 8)>>>(theta);
    gemm_mma_kernel<<<dim3(NN / TN, BB / TM, SPLIT), 256, GEMM_SMEM>>>();
    pairwise_kernel<<<KK, BB>>>(bias, out);
}